// round 4
// baseline (speedup 1.0000x reference)
#include <cuda_runtime.h>

// Shapes (fixed)
#define B_ 32
#define P_ 196
#define D_ 512
#define H_ 8
#define U_ 4
#define C_ 500

#define KNOWN_ELEMS (B_ * C_ * (H_ + 3) * D_)   // 90,112,000
#define UNK_ELEMS   (B_ * (U_ + 3) * D_)        // 114,688

#define NBLK 444            // 148 SMs x 3 blocks, co-resident (66KB smem each)
#define TPAD 516            // padded row stride (floats) for proj tiles
#define SMEM_BYTES (2 * 16 * TPAD * 4)   // 66048 B

// Scratch (device globals — no allocation allowed)
__device__ float g_dom[B_ * D_];
__device__ float g_sem[B_ * H_ * D_];
__device__ float g_scores[B_ * P_ * H_];
__device__ unsigned g_bar_count;
__device__ volatile unsigned g_bar_gen;

// ---------------------------------------------------------------------------
// Grid-wide barrier (all NBLK blocks co-resident). gen is monotonic across
// graph replays — pure sync state, output-deterministic.
// ---------------------------------------------------------------------------
__device__ __forceinline__ void grid_barrier() {
    __syncthreads();
    if (threadIdx.x == 0) {
        __threadfence();
        unsigned gen = g_bar_gen;
        if (atomicAdd(&g_bar_count, 1u) == NBLK - 1) {
            g_bar_count = 0;
            __threadfence();
            g_bar_gen = gen + 1;
        } else {
            while (g_bar_gen == gen) __nanosleep(64);
        }
        __threadfence();
    }
    __syncthreads();
}

// ---------------------------------------------------------------------------
// One persistent kernel, 4 phases separated by grid barriers.
// ---------------------------------------------------------------------------
__global__ __launch_bounds__(256, 3)
void k_fused(const float* __restrict__ patch,
             const float* __restrict__ gf,
             const float* __restrict__ query,
             const float* __restrict__ domW,
             const float* __restrict__ domb,
             const float* __restrict__ semW,
             const float* __restrict__ semb,
             const float4* __restrict__ usem,
             const float4* __restrict__ pre,
             const float4* __restrict__ suf,
             const float4* __restrict__ upre,
             const float4* __restrict__ usuf,
             float4* __restrict__ out,        // known prompts
             float4* __restrict__ unk_out,    // unknown prompts
             float* __restrict__ sem_out)     // semantic_tokens (in d_out)
{
    extern __shared__ float sh[];
    const int tid  = threadIdx.x;
    const int warp = tid >> 5, lane = tid & 31;

    // ============== Phase A: scores[b,p,h] = patch[b,p,:] . query[h,:] =====
    {
        float4* q_sh = (float4*)sh;                 // 8 * 128 float4 = 16 KB
        for (int i = tid; i < H_ * 128; i += 256)
            q_sh[i] = ((const float4*)query)[i];
        __syncthreads();

        for (int gw = blockIdx.x * 8 + warp; gw < B_ * P_; gw += NBLK * 8) {
            const int b = gw / P_;
            const int p = gw - b * P_;
            const float4* row = (const float4*)(patch + ((size_t)b * P_ + p) * D_);
            float acc[H_];
#pragma unroll
            for (int h = 0; h < H_; h++) acc[h] = 0.f;
#pragma unroll
            for (int i = 0; i < 4; i++) {
                float4 x = row[lane + i * 32];
#pragma unroll
                for (int h = 0; h < H_; h++) {
                    float4 q = q_sh[h * 128 + lane + i * 32];
                    acc[h] += x.x * q.x + x.y * q.y + x.z * q.z + x.w * q.w;
                }
            }
#pragma unroll
            for (int h = 0; h < H_; h++) {
#pragma unroll
                for (int o = 16; o; o >>= 1)
                    acc[h] += __shfl_xor_sync(0xffffffffu, acc[h], o);
            }
            if (lane == 0) {
                float* s = g_scores + ((size_t)b * P_ + p) * H_;
#pragma unroll
                for (int h = 0; h < H_; h++) s[h] = acc[h];
            }
        }
    }
    grid_barrier();

    // ============== Phase B: softmax over P + weighted pooling ==============
    // 128 tiles: (b, d-tile of 128). 256 threads = 128 d x 2 p-halves.
    for (int t = blockIdx.x; t < B_ * 4; t += NBLK) {
        const int b  = t >> 2;
        const int dt = t & 3;

        float* w_sh  = sh;                    // P_*H_ = 1568 floats
        float* mmax  = sh + 1568;             // 8
        float* inv_s = sh + 1576;             // 8
        float* psum  = sh + 1600;             // 128*8 = 1024 floats

        const float* sc = g_scores + (size_t)b * P_ * H_;
        for (int i = tid; i < P_ * H_; i += 256) w_sh[i] = sc[i];
        __syncthreads();

        // warp h computes stats for head h (8 warps = 8 heads)
        {
            const int h = warp;
            float m = -1e30f;
            for (int p = lane; p < P_; p += 32) m = fmaxf(m, w_sh[p * H_ + h]);
#pragma unroll
            for (int o = 16; o; o >>= 1) m = fmaxf(m, __shfl_xor_sync(0xffffffffu, m, o));
            float s = 0.f;
            for (int p = lane; p < P_; p += 32) s += __expf(w_sh[p * H_ + h] - m);
#pragma unroll
            for (int o = 16; o; o >>= 1) s += __shfl_xor_sync(0xffffffffu, s, o);
            if (lane == 0) { mmax[h] = m; inv_s[h] = 1.f / s; }
        }
        __syncthreads();
        for (int i = tid; i < P_ * H_; i += 256) {
            int h = i & (H_ - 1);
            w_sh[i] = __expf(w_sh[i] - mmax[h]) * inv_s[h];
        }
        __syncthreads();

        const int d_local = tid & 127;
        const int phalf   = tid >> 7;           // 0 or 1
        const int d       = dt * 128 + d_local;
        const int p0      = phalf * 98;
        const float* pb = patch + (size_t)b * P_ * D_ + d;

        float acc[H_];
#pragma unroll
        for (int h = 0; h < H_; h++) acc[h] = 0.f;
        for (int p = p0; p < p0 + 98; p += 2) {
            float x0 = pb[(p + 0) * D_];
            float x1 = pb[(p + 1) * D_];
#pragma unroll
            for (int h = 0; h < H_; h++) {
                acc[h] = fmaf(w_sh[(p + 0) * H_ + h], x0, acc[h]);
                acc[h] = fmaf(w_sh[(p + 1) * H_ + h], x1, acc[h]);
            }
        }
        if (phalf == 1) {
#pragma unroll
            for (int h = 0; h < H_; h++) psum[d_local * H_ + h] = acc[h];
        }
        __syncthreads();
        if (phalf == 0) {
#pragma unroll
            for (int h = 0; h < H_; h++) {
                float v = acc[h] + psum[d_local * H_ + h];
                sem_out[((size_t)b * H_ + h) * D_ + d] = v;
            }
        }
        __syncthreads();
    }
    grid_barrier();

    // ============== Phase C: projections (sem heads + domain) ===============
    // 576 tiles: y(9: 8 heads + dom) x e-tile(32 of 16 rows) x b-half(2 of 16)
    for (int t = blockIdx.x; t < 9 * 32 * 2; t += NBLK) {
        const int y  = t / 64;
        const int r  = t - y * 64;
        const int e0 = (r >> 1) * 16;
        const int b0 = (r & 1) * 16;
        const bool dom = (y == 8);

        float* Tsh = sh;                  // [16][TPAD]
        float* Wsh = sh + 16 * TPAD;      // [16][TPAD]

        const float* Tbase   = dom ? gf : (sem_out + (size_t)y * D_);
        const size_t Tstride = dom ? (size_t)D_ : (size_t)H_ * D_;
        const float* Wbase   = dom ? (domW + (size_t)e0 * D_)
                                   : (semW + ((size_t)y * D_ + e0) * D_);

        for (int i = tid; i < 16 * 128; i += 256) {
            int rr = i >> 7, j = i & 127;
            ((float4*)(Tsh + rr * TPAD))[j] =
                ((const float4*)(Tbase + (size_t)(b0 + rr) * Tstride))[j];
            ((float4*)(Wsh + rr * TPAD))[j] = ((const float4*)Wbase)[rr * 128 + j];
        }
        __syncthreads();

        const int e_local = tid & 15;
        const int b_local = tid >> 4;
        const float4* wrow = (const float4*)(Wsh + e_local * TPAD);
        const float4* trow = (const float4*)(Tsh + b_local * TPAD);
        float a = 0.f;
#pragma unroll 8
        for (int i = 0; i < 128; i++) {
            float4 w = wrow[i];
            float4 x = trow[i];
            a += w.x * x.x + w.y * x.y + w.z * x.z + w.w * x.w;
        }
        const int e = e0 + e_local;
        const int b = b0 + b_local;
        if (dom)  g_dom[b * D_ + e] = a + domb[e];
        else      g_sem[((size_t)b * H_ + y) * D_ + e] = a + semb[y * D_ + e];
        __syncthreads();
    }
    grid_barrier();

    // ============== Phase D: prompt writer (HBM-bound, 361 MB stores) =======
    for (int it = blockIdx.x; it < B_ * C_ + B_; it += NBLK) {
        if (it < B_ * C_) {
            const int b = it / C_;
            const int c = it - b * C_;
            float4* o = out + (size_t)it * (11 * 128);
            const float4* dm   = ((const float4*)g_dom) + b * 128;
            const float4* sm   = ((const float4*)g_sem) + (size_t)b * H_ * 128;
            const float4* prow = pre + (size_t)c * 128;
            const float4* srow = suf + (size_t)c * 128;
            for (int i = tid; i < 11 * 128; i += 256) {
                const int tk = i >> 7, j = i & 127;
                float4 v;
                if (tk == 0)       v = prow[j];
                else if (tk == 1)  v = dm[j];
                else if (tk < 10)  v = sm[(tk - 2) * 128 + j];
                else               v = srow[j];
                __stcs(&o[i], v);
            }
        } else {
            const int b = it - B_ * C_;
            float4* o = unk_out + (size_t)b * 7 * 128;
            const float4* dm = ((const float4*)g_dom) + b * 128;
            for (int i = tid; i < 7 * 128; i += 256) {
                const int tk = i >> 7, j = i & 127;
                float4 v;
                if (tk == 0)      v = upre[j];
                else if (tk == 1) v = dm[j];
                else if (tk < 6)  v = usem[(tk - 2) * 128 + j];
                else              v = usuf[j];
                __stcs(&o[i], v);
            }
        }
    }
}

// ---------------------------------------------------------------------------
extern "C" void kernel_launch(void* const* d_in, const int* in_sizes, int n_in,
                              void* d_out, int out_size) {
    const float* patch = (const float*)d_in[0];   // (32,196,512)
    const float* gf    = (const float*)d_in[1];   // (32,512)
    const float* query = (const float*)d_in[2];   // (8,512)
    const float* domW  = (const float*)d_in[3];   // (512,512)
    const float* domb  = (const float*)d_in[4];   // (512,)
    const float* semW  = (const float*)d_in[5];   // (8,512,512)
    const float* semb  = (const float*)d_in[6];   // (8,512)
    const float* usem  = (const float*)d_in[7];   // (4,512)
    const float* pre   = (const float*)d_in[8];   // (500,1,512)
    const float* suf   = (const float*)d_in[9];   // (500,1,512)
    const float* upre  = (const float*)d_in[10];  // (1,512)
    const float* usuf  = (const float*)d_in[11];  // (1,512)

    float* out     = (float*)d_out;
    float* unk_out = out + (size_t)KNOWN_ELEMS;
    float* sem_out = out + (size_t)KNOWN_ELEMS + UNK_ELEMS;

    cudaFuncSetAttribute(k_fused, cudaFuncAttributeMaxDynamicSharedMemorySize,
                         SMEM_BYTES);

    k_fused<<<NBLK, 256, SMEM_BYTES>>>(
        patch, gf, query, domW, domb, semW, semb,
        (const float4*)usem, (const float4*)pre, (const float4*)suf,
        (const float4*)upre, (const float4*)usuf,
        (float4*)out, (float4*)unk_out, sem_out);
}